// round 1
// baseline (speedup 1.0000x reference)
#include <cuda_runtime.h>
#include <math.h>

#define D 8192
#define M_TIME 16
#define KWTA_K (D / 8)

// Scratch (device globals — no allocation allowed)
__device__ float g_x[D];
__device__ float g_rpre[D];
__device__ float g_k[D];
__device__ float g_v[D];
__device__ float g_y[D];
__device__ float g_h[D];

__device__ __forceinline__ float softplusf(float x) {
    // log(1 + exp(x)), stable
    if (x > 20.f) return x;
    if (x < -20.f) return expf(x);
    return log1pf(expf(x));
}

// ---------------------------------------------------------------------------
// K0: x = rmsnorm(x_in + pred) * g_norm
// ---------------------------------------------------------------------------
__global__ void rmsnorm_kernel(const float* __restrict__ x_in,
                               const float* __restrict__ pred,
                               const float* __restrict__ g_norm) {
    __shared__ float red[256];
    float s = 0.f;
    for (int i = threadIdx.x; i < D; i += 256) {
        float t = x_in[i] + pred[i];
        s += t * t;
    }
    red[threadIdx.x] = s;
    __syncthreads();
    for (int o = 128; o > 0; o >>= 1) {
        if (threadIdx.x < o) red[threadIdx.x] += red[threadIdx.x + o];
        __syncthreads();
    }
    float scale = rsqrtf(red[0] / (float)D + 1e-6f);
    for (int i = threadIdx.x; i < D; i += 256) {
        g_x[i] = (x_in[i] + pred[i]) * scale * g_norm[i];
    }
}

// ---------------------------------------------------------------------------
// K1: fused 3-matrix GEMV. warp-per-row, 8 rows (8 warps) per block.
// grid.x = 3 * (D/8) = 3072
// ---------------------------------------------------------------------------
__global__ void __launch_bounds__(256) gemv3_kernel(const float* __restrict__ Wr,
                                                    const float* __restrict__ Wk,
                                                    const float* __restrict__ Wv) {
    const int blocks_per_mat = D / 8;  // 1024
    int mat = blockIdx.x / blocks_per_mat;
    int rowbase = (blockIdx.x % blocks_per_mat) * 8;
    const float* W = (mat == 0) ? Wr : ((mat == 1) ? Wk : Wv);

    int warp = threadIdx.x >> 5;
    int lane = threadIdx.x & 31;
    int row = rowbase + warp;

    const float4* wrow = (const float4*)(W + (size_t)row * D);
    const float4* xv = (const float4*)g_x;

    float acc0 = 0.f, acc1 = 0.f;
    int j = lane;
#pragma unroll 8
    for (int it = 0; it < 64; it += 2) {
        float4 w4 = wrow[j];
        float4 x4 = xv[j];
        acc0 += w4.x * x4.x + w4.y * x4.y + w4.z * x4.z + w4.w * x4.w;
        float4 w5 = wrow[j + 32];
        float4 x5 = xv[j + 32];
        acc1 += w5.x * x5.x + w5.y * x5.y + w5.z * x5.z + w5.w * x5.w;
        j += 64;
    }
    float acc = acc0 + acc1;
#pragma unroll
    for (int o = 16; o > 0; o >>= 1) acc += __shfl_xor_sync(0xFFFFFFFFu, acc, o);

    if (lane == 0) {
        if (mat == 0) g_rpre[row] = acc;
        else if (mat == 1) g_k[row] = acc;
        else g_v[row] = acc;
    }
}

// ---------------------------------------------------------------------------
// K2: elementwise (decay, RoPE, Kalman gate) -> y
// ---------------------------------------------------------------------------
__global__ void elemwise_kernel(const float* __restrict__ step_pos,
                                const float* __restrict__ state_num,
                                const float* __restrict__ state_den,
                                const float* __restrict__ state_var,
                                const float* __restrict__ raw_decay,
                                const float* __restrict__ pn_param,
                                const float* __restrict__ on_param,
                                const float* __restrict__ W_time) {
    int i = blockIdx.x * 256 + threadIdx.x;
    if (i >= D) return;

    float k = g_k[i];
    float v = g_v[i];
    if (i < 2 * M_TIME) {
        int m = i >> 1;
        float th = step_pos[0] * W_time[m];
        float c, s;
        sincosf(th, &s, &c);  // s = sin, c = cos
        float v0 = g_v[2 * m];
        float v1 = g_v[2 * m + 1];
        v = (i & 1) ? (v0 * s + v1 * c) : (v0 * c - v1 * s);
    }

    float sp = softplusf(raw_decay[i]);
    float rate = fmaxf(-sp, -30.f);
    float lam = fmaxf(expf(rate), 1e-6f);
    float pn = fminf(fmaxf(softplusf(pn_param[0]), 1e-6f), 1e4f);
    float on = fminf(fmaxf(softplusf(on_param[0]), 1e-6f), 1e4f);

    float sn = state_num[i] * lam;
    float sd = state_den[i] * lam;
    float sv = state_var[i] * lam * lam + pn;

    float r = 1.f / (1.f + expf(-g_rpre[i]));
    float w = expf(fminf(k, 30.f));
    float pred_state = sn / (sd + 1e-6f);
    float msg = w * v;
    float resid = msg - pred_state;
    float obs_var = expf(fminf(-k, 30.f)) * on + 1e-6f;
    float gain = sv / (sv + obs_var);
    gain = fminf(fmaxf(gain, 1e-6f), 1.f - 1e-6f);
    float new_state = pred_state + gain * resid;
    g_y[i] = r * new_state;
}

// ---------------------------------------------------------------------------
// K3: h = x + Wo @ y.  warp-per-row, 8 rows/block, 1024 blocks.
// ---------------------------------------------------------------------------
__global__ void __launch_bounds__(256) gemv_o_kernel(const float* __restrict__ Wo) {
    int rowbase = blockIdx.x * 8;
    int warp = threadIdx.x >> 5;
    int lane = threadIdx.x & 31;
    int row = rowbase + warp;

    const float4* wrow = (const float4*)(Wo + (size_t)row * D);
    const float4* yv = (const float4*)g_y;

    float acc0 = 0.f, acc1 = 0.f;
    int j = lane;
#pragma unroll 8
    for (int it = 0; it < 64; it += 2) {
        float4 w4 = wrow[j];
        float4 y4 = yv[j];
        acc0 += w4.x * y4.x + w4.y * y4.y + w4.z * y4.z + w4.w * y4.w;
        float4 w5 = wrow[j + 32];
        float4 y5 = yv[j + 32];
        acc1 += w5.x * y5.x + w5.y * y5.y + w5.z * y5.z + w5.w * y5.w;
        j += 64;
    }
    float acc = acc0 + acc1;
#pragma unroll
    for (int o = 16; o > 0; o >>= 1) acc += __shfl_xor_sync(0xFFFFFFFFu, acc, o);

    if (lane == 0) g_h[row] = g_x[row] + acc;
}

// ---------------------------------------------------------------------------
// K4: exact KWTA_K-th-largest (radix select on monotonic keys) + threshold
// Single block, 256 threads.
// ---------------------------------------------------------------------------
__global__ void topk_kernel(float* __restrict__ out) {
    __shared__ unsigned hist[256];
    __shared__ unsigned s_prefix;
    __shared__ int s_K;
    __shared__ float s_thresh;

    if (threadIdx.x == 0) { s_prefix = 0u; s_K = KWTA_K; }
    __syncthreads();

    for (int pass = 3; pass >= 0; pass--) {
        hist[threadIdx.x] = 0u;
        __syncthreads();
        unsigned prefmask = (pass == 3) ? 0u : (0xFFFFFFFFu << ((pass + 1) * 8));
        unsigned pref = s_prefix;
        for (int i = threadIdx.x; i < D; i += 256) {
            unsigned u = __float_as_uint(g_h[i]);
            unsigned key = (u & 0x80000000u) ? ~u : (u | 0x80000000u);
            if ((key & prefmask) == (pref & prefmask)) {
                atomicAdd(&hist[(key >> (pass * 8)) & 255u], 1u);
            }
        }
        __syncthreads();
        if (threadIdx.x == 0) {
            int K = s_K;
            unsigned cum = 0;
            int b = 255;
            for (; b >= 0; b--) {
                cum += hist[b];
                if ((int)cum >= K) break;
            }
            s_K = K - (int)(cum - hist[b]);
            s_prefix = s_prefix | ((unsigned)b << (pass * 8));
        }
        __syncthreads();
    }

    if (threadIdx.x == 0) {
        unsigned key = s_prefix;
        unsigned u = (key & 0x80000000u) ? (key ^ 0x80000000u) : ~key;
        s_thresh = __uint_as_float(u);
    }
    __syncthreads();

    float th = s_thresh;
    for (int i = threadIdx.x; i < D; i += 256) {
        float h = g_h[i];
        out[i] = (h >= th) ? h : 0.f;
    }
}

// ---------------------------------------------------------------------------
// Launch
// Input order: 0 x_in, 1 step_pos, 2 pred, 3 state_num, 4 state_den,
// 5 state_var, 6 Wr, 7 Wk, 8 Wv, 9 Wo, 10 raw_decay, 11 pn_param,
// 12 on_param, 13 g_norm, 14 W_time
// ---------------------------------------------------------------------------
extern "C" void kernel_launch(void* const* d_in, const int* in_sizes, int n_in,
                              void* d_out, int out_size) {
    const float* x_in      = (const float*)d_in[0];
    const float* step_pos  = (const float*)d_in[1];
    const float* pred      = (const float*)d_in[2];
    const float* state_num = (const float*)d_in[3];
    const float* state_den = (const float*)d_in[4];
    const float* state_var = (const float*)d_in[5];
    const float* Wr        = (const float*)d_in[6];
    const float* Wk        = (const float*)d_in[7];
    const float* Wv        = (const float*)d_in[8];
    const float* Wo        = (const float*)d_in[9];
    const float* raw_decay = (const float*)d_in[10];
    const float* pn_param  = (const float*)d_in[11];
    const float* on_param  = (const float*)d_in[12];
    const float* g_norm    = (const float*)d_in[13];
    const float* W_time    = (const float*)d_in[14];
    float* out = (float*)d_out;

    rmsnorm_kernel<<<1, 256>>>(x_in, pred, g_norm);
    gemv3_kernel<<<3 * (D / 8), 256>>>(Wr, Wk, Wv);
    elemwise_kernel<<<D / 256, 256>>>(step_pos, state_num, state_den, state_var,
                                      raw_decay, pn_param, on_param, W_time);
    gemv_o_kernel<<<D / 8, 256>>>(Wo);
    topk_kernel<<<1, 256>>>(out);
}

// round 2
// speedup vs baseline: 1.0168x; 1.0168x over previous
#include <cuda_runtime.h>
#include <math.h>

#define D 8192
#define M_TIME 16
#define KWTA_K (D / 8)
#define ROWS 8          // rows per block in GEMV
#define GTHREADS 256    // threads per GEMV block
#define KITERS (D / 4 / GTHREADS)   // 8 float4 column iterations per thread

// Scratch (device globals — no allocation allowed)
__device__ float g_x[D];
__device__ float g_rpre[D];
__device__ float g_k[D];
__device__ float g_v[D];
__device__ float g_y[D];
__device__ float g_h[D];

__device__ __forceinline__ float softplusf(float x) {
    if (x > 20.f) return x;
    if (x < -20.f) return expf(x);
    return log1pf(expf(x));
}

// Streaming vector load with 256B L2 prefetch hint (W is read exactly once)
__device__ __forceinline__ float4 ldg_stream(const float4* p) {
    float4 v;
    asm volatile("ld.global.nc.L2::256B.v4.f32 {%0,%1,%2,%3}, [%4];"
                 : "=f"(v.x), "=f"(v.y), "=f"(v.z), "=f"(v.w)
                 : "l"(p));
    return v;
}

// ---------------------------------------------------------------------------
// K0: x = rmsnorm(x_in + pred) * g_norm     (1 block, 1024 threads)
// ---------------------------------------------------------------------------
__global__ void rmsnorm_kernel(const float* __restrict__ x_in,
                               const float* __restrict__ pred,
                               const float* __restrict__ g_norm) {
    __shared__ float red[1024];
    float s = 0.f;
    for (int i = threadIdx.x; i < D; i += 1024) {
        float t = x_in[i] + pred[i];
        s += t * t;
    }
    red[threadIdx.x] = s;
    __syncthreads();
    for (int o = 512; o > 0; o >>= 1) {
        if (threadIdx.x < o) red[threadIdx.x] += red[threadIdx.x + o];
        __syncthreads();
    }
    float scale = rsqrtf(red[0] / (float)D + 1e-6f);
    for (int i = threadIdx.x; i < D; i += 1024) {
        g_x[i] = (x_in[i] + pred[i]) * scale * g_norm[i];
    }
}

// ---------------------------------------------------------------------------
// GEMV core: one block computes ROWS consecutive rows of W @ vec.
// Threads span columns; each x float4 feeds 8 independent W loads (MLP=8).
// ---------------------------------------------------------------------------
__device__ __forceinline__ void gemv_rows(const float* __restrict__ W,
                                          const float* __restrict__ vec,
                                          int rowbase, float* acc_out /*[ROWS] via smem path*/,
                                          float* __restrict__ dst,
                                          const float* __restrict__ add_src) {
    const float4* xv = (const float4*)vec;
    const float4* wrow[ROWS];
#pragma unroll
    for (int r = 0; r < ROWS; r++)
        wrow[r] = (const float4*)(W + (size_t)(rowbase + r) * D);

    float acc[ROWS];
#pragma unroll
    for (int r = 0; r < ROWS; r++) acc[r] = 0.f;

#pragma unroll
    for (int k = 0; k < KITERS; k++) {
        int c = threadIdx.x + k * GTHREADS;
        float4 x4 = xv[c];
        float4 w[ROWS];
#pragma unroll
        for (int r = 0; r < ROWS; r++) w[r] = ldg_stream(&wrow[r][c]);
#pragma unroll
        for (int r = 0; r < ROWS; r++) {
            acc[r] += w[r].x * x4.x + w[r].y * x4.y + w[r].z * x4.z + w[r].w * x4.w;
        }
    }

    // warp reduce each row accumulator
#pragma unroll
    for (int r = 0; r < ROWS; r++) {
#pragma unroll
        for (int o = 16; o > 0; o >>= 1)
            acc[r] += __shfl_xor_sync(0xFFFFFFFFu, acc[r], o);
    }

    __shared__ float sred[GTHREADS / 32][ROWS];
    int warp = threadIdx.x >> 5;
    int lane = threadIdx.x & 31;
    if (lane == 0) {
#pragma unroll
        for (int r = 0; r < ROWS; r++) sred[warp][r] = acc[r];
    }
    __syncthreads();
    if (threadIdx.x < ROWS) {
        float s = 0.f;
#pragma unroll
        for (int w = 0; w < GTHREADS / 32; w++) s += sred[w][threadIdx.x];
        int row = rowbase + threadIdx.x;
        dst[row] = add_src ? (add_src[row] + s) : s;
    }
}

// K1: fused Wr/Wk/Wv GEMV. grid.x = 3 * D/ROWS = 3072
__global__ void __launch_bounds__(GTHREADS) gemv3_kernel(const float* __restrict__ Wr,
                                                         const float* __restrict__ Wk,
                                                         const float* __restrict__ Wv) {
    const int blocks_per_mat = D / ROWS;  // 1024
    int mat = blockIdx.x / blocks_per_mat;
    int rowbase = (blockIdx.x % blocks_per_mat) * ROWS;
    const float* W = (mat == 0) ? Wr : ((mat == 1) ? Wk : Wv);
    float* dst = (mat == 0) ? g_rpre : ((mat == 1) ? g_k : g_v);
    gemv_rows(W, g_x, rowbase, nullptr, dst, nullptr);
}

// K3: h = x + Wo @ y. grid.x = D/ROWS = 1024
__global__ void __launch_bounds__(GTHREADS) gemv_o_kernel(const float* __restrict__ Wo) {
    int rowbase = blockIdx.x * ROWS;
    gemv_rows(Wo, g_y, rowbase, nullptr, g_h, g_x);
}

// ---------------------------------------------------------------------------
// K2: elementwise (decay, RoPE, Kalman gate) -> y
// ---------------------------------------------------------------------------
__global__ void elemwise_kernel(const float* __restrict__ step_pos,
                                const float* __restrict__ state_num,
                                const float* __restrict__ state_den,
                                const float* __restrict__ state_var,
                                const float* __restrict__ raw_decay,
                                const float* __restrict__ pn_param,
                                const float* __restrict__ on_param,
                                const float* __restrict__ W_time) {
    int i = blockIdx.x * 256 + threadIdx.x;
    if (i >= D) return;

    float k = g_k[i];
    float v = g_v[i];
    if (i < 2 * M_TIME) {
        int m = i >> 1;
        float th = step_pos[0] * W_time[m];
        float c, s;
        sincosf(th, &s, &c);
        float v0 = g_v[2 * m];
        float v1 = g_v[2 * m + 1];
        v = (i & 1) ? (v0 * s + v1 * c) : (v0 * c - v1 * s);
    }

    float sp = softplusf(raw_decay[i]);
    float rate = fmaxf(-sp, -30.f);
    float lam = fmaxf(expf(rate), 1e-6f);
    float pn = fminf(fmaxf(softplusf(pn_param[0]), 1e-6f), 1e4f);
    float on = fminf(fmaxf(softplusf(on_param[0]), 1e-6f), 1e4f);

    float sn = state_num[i] * lam;
    float sd = state_den[i] * lam;
    float sv = state_var[i] * lam * lam + pn;

    float r = 1.f / (1.f + expf(-g_rpre[i]));
    float w = expf(fminf(k, 30.f));
    float pred_state = sn / (sd + 1e-6f);
    float msg = w * v;
    float resid = msg - pred_state;
    float obs_var = expf(fminf(-k, 30.f)) * on + 1e-6f;
    float gain = sv / (sv + obs_var);
    gain = fminf(fmaxf(gain, 1e-6f), 1.f - 1e-6f);
    float new_state = pred_state + gain * resid;
    g_y[i] = r * new_state;
}

// ---------------------------------------------------------------------------
// K4: exact KWTA_K-th-largest (radix select) + threshold. 1 block, 1024 thr.
// ---------------------------------------------------------------------------
__global__ void topk_kernel(float* __restrict__ out) {
    __shared__ unsigned hist[256];
    __shared__ unsigned s_prefix;
    __shared__ int s_K;
    __shared__ float s_thresh;

    if (threadIdx.x == 0) { s_prefix = 0u; s_K = KWTA_K; }
    __syncthreads();

    for (int pass = 3; pass >= 0; pass--) {
        if (threadIdx.x < 256) hist[threadIdx.x] = 0u;
        __syncthreads();
        unsigned prefmask = (pass == 3) ? 0u : (0xFFFFFFFFu << ((pass + 1) * 8));
        unsigned pref = s_prefix;
        for (int i = threadIdx.x; i < D; i += 1024) {
            unsigned u = __float_as_uint(g_h[i]);
            unsigned key = (u & 0x80000000u) ? ~u : (u | 0x80000000u);
            if ((key & prefmask) == (pref & prefmask)) {
                atomicAdd(&hist[(key >> (pass * 8)) & 255u], 1u);
            }
        }
        __syncthreads();
        if (threadIdx.x == 0) {
            int K = s_K;
            unsigned cum = 0;
            int b = 255;
            for (; b >= 0; b--) {
                cum += hist[b];
                if ((int)cum >= K) break;
            }
            s_K = K - (int)(cum - hist[b]);
            s_prefix = s_prefix | ((unsigned)b << (pass * 8));
        }
        __syncthreads();
    }

    if (threadIdx.x == 0) {
        unsigned key = s_prefix;
        unsigned u = (key & 0x80000000u) ? (key ^ 0x80000000u) : ~key;
        s_thresh = __uint_as_float(u);
    }
    __syncthreads();

    float th = s_thresh;
    for (int i = threadIdx.x; i < D; i += 1024) {
        float h = g_h[i];
        out[i] = (h >= th) ? h : 0.f;
    }
}

// ---------------------------------------------------------------------------
// Launch
// ---------------------------------------------------------------------------
extern "C" void kernel_launch(void* const* d_in, const int* in_sizes, int n_in,
                              void* d_out, int out_size) {
    const float* x_in      = (const float*)d_in[0];
    const float* step_pos  = (const float*)d_in[1];
    const float* pred      = (const float*)d_in[2];
    const float* state_num = (const float*)d_in[3];
    const float* state_den = (const float*)d_in[4];
    const float* state_var = (const float*)d_in[5];
    const float* Wr        = (const float*)d_in[6];
    const float* Wk        = (const float*)d_in[7];
    const float* Wv        = (const float*)d_in[8];
    const float* Wo        = (const float*)d_in[9];
    const float* raw_decay = (const float*)d_in[10];
    const float* pn_param  = (const float*)d_in[11];
    const float* on_param  = (const float*)d_in[12];
    const float* g_norm    = (const float*)d_in[13];
    const float* W_time    = (const float*)d_in[14];
    float* out = (float*)d_out;

    rmsnorm_kernel<<<1, 1024>>>(x_in, pred, g_norm);
    gemv3_kernel<<<3 * (D / ROWS), GTHREADS>>>(Wr, Wk, Wv);
    elemwise_kernel<<<D / 256, 256>>>(step_pos, state_num, state_den, state_var,
                                      raw_decay, pn_param, on_param, W_time);
    gemv_o_kernel<<<D / ROWS, GTHREADS>>>(Wo);
    topk_kernel<<<1, 1024>>>(out);
}

// round 3
// speedup vs baseline: 1.0735x; 1.0557x over previous
#include <cuda_runtime.h>
#include <math.h>

#define D 8192
#define M_TIME 16
#define KWTA_K (D / 8)
#define ROWS 8
#define GTHREADS 256
#define CHUNK 1024                 // floats per row per stage
#define C4 (CHUNK / 4)             // 256 float4 per row per stage == GTHREADS
#define NCHUNK (D / CHUNK)         // 8
#define STAGE_F4 (ROWS * C4)       // float4 per stage
#define SMEM_BYTES (2 * STAGE_F4 * 16)   // 64 KB double buffer

// Scratch (device globals — no allocation allowed)
__device__ float g_x[D];
__device__ float g_rpre[D];
__device__ float g_k[D];
__device__ float g_v[D];
__device__ float g_y[D];
__device__ float g_h[D];

__device__ __forceinline__ float softplusf(float x) {
    if (x > 20.f) return x;
    if (x < -20.f) return expf(x);
    return log1pf(expf(x));
}

__device__ __forceinline__ void cp_async16(void* smem_dst, const void* gmem_src) {
    unsigned saddr = (unsigned)__cvta_generic_to_shared(smem_dst);
    asm volatile("cp.async.cg.shared.global [%0], [%1], 16;\n"
                 :: "r"(saddr), "l"(gmem_src));
}
__device__ __forceinline__ void cp_commit() {
    asm volatile("cp.async.commit_group;\n");
}
template <int N>
__device__ __forceinline__ void cp_wait() {
    asm volatile("cp.async.wait_group %0;\n" :: "n"(N));
}

// ---------------------------------------------------------------------------
// K0: x = rmsnorm(x_in + pred) * g_norm     (1 block, 1024 threads)
// ---------------------------------------------------------------------------
__global__ void rmsnorm_kernel(const float* __restrict__ x_in,
                               const float* __restrict__ pred,
                               const float* __restrict__ g_norm) {
    __shared__ float red[1024];
    float s = 0.f;
    for (int i = threadIdx.x; i < D; i += 1024) {
        float t = x_in[i] + pred[i];
        s += t * t;
    }
    red[threadIdx.x] = s;
    __syncthreads();
    for (int o = 512; o > 0; o >>= 1) {
        if (threadIdx.x < o) red[threadIdx.x] += red[threadIdx.x + o];
        __syncthreads();
    }
    float scale = rsqrtf(red[0] / (float)D + 1e-6f);
    for (int i = threadIdx.x; i < D; i += 1024) {
        g_x[i] = (x_in[i] + pred[i]) * scale * g_norm[i];
    }
}

// ---------------------------------------------------------------------------
// GEMV core: block computes ROWS rows of W @ vec via cp.async double-buffer.
// Thread t owns float4 column t within each 1024-float chunk, for all 8 rows.
// ---------------------------------------------------------------------------
__device__ __forceinline__ void gemv_rows_async(const float* __restrict__ W,
                                                const float* __restrict__ vec,
                                                int rowbase,
                                                float* __restrict__ dst,
                                                const float* __restrict__ add_src) {
    extern __shared__ float4 sbuf[];   // [2][ROWS][C4]
    const int t = threadIdx.x;
    const float4* xv = (const float4*)vec;
    const float* wbase = W + (size_t)rowbase * D + t * 4;

    // Prologue: stage 0 <- chunk 0
#pragma unroll
    for (int r = 0; r < ROWS; r++)
        cp_async16(&sbuf[r * C4 + t], wbase + (size_t)r * D);
    cp_commit();

    float acc[ROWS];
#pragma unroll
    for (int r = 0; r < ROWS; r++) acc[r] = 0.f;

#pragma unroll
    for (int ci = 0; ci < NCHUNK; ci++) {
        const int cur = ci & 1;
        if (ci + 1 < NCHUNK) {
            const int nxt = (ci + 1) & 1;
            const float* src = wbase + (ci + 1) * CHUNK;
#pragma unroll
            for (int r = 0; r < ROWS; r++)
                cp_async16(&sbuf[nxt * STAGE_F4 + r * C4 + t], src + (size_t)r * D);
            cp_commit();
            cp_wait<1>();
        } else {
            cp_wait<0>();
        }
        __syncthreads();

        float4 x4 = xv[ci * C4 + t];
        const float4* sb = &sbuf[cur * STAGE_F4 + t];
#pragma unroll
        for (int r = 0; r < ROWS; r++) {
            float4 w4 = sb[r * C4];
            acc[r] += w4.x * x4.x + w4.y * x4.y + w4.z * x4.z + w4.w * x4.w;
        }
        __syncthreads();
    }

    // warp reduce each row accumulator
#pragma unroll
    for (int r = 0; r < ROWS; r++) {
#pragma unroll
        for (int o = 16; o > 0; o >>= 1)
            acc[r] += __shfl_xor_sync(0xFFFFFFFFu, acc[r], o);
    }

    __shared__ float sred[GTHREADS / 32][ROWS];
    int warp = t >> 5;
    int lane = t & 31;
    if (lane == 0) {
#pragma unroll
        for (int r = 0; r < ROWS; r++) sred[warp][r] = acc[r];
    }
    __syncthreads();
    if (t < ROWS) {
        float s = 0.f;
#pragma unroll
        for (int w = 0; w < GTHREADS / 32; w++) s += sred[w][t];
        int row = rowbase + t;
        dst[row] = add_src ? (add_src[row] + s) : s;
    }
}

// K1: fused Wr/Wk/Wv GEMV. grid.x = 3 * D/ROWS = 3072
__global__ void __launch_bounds__(GTHREADS) gemv3_kernel(const float* __restrict__ Wr,
                                                         const float* __restrict__ Wk,
                                                         const float* __restrict__ Wv) {
    const int blocks_per_mat = D / ROWS;  // 1024
    int mat = blockIdx.x / blocks_per_mat;
    int rowbase = (blockIdx.x % blocks_per_mat) * ROWS;
    const float* W = (mat == 0) ? Wr : ((mat == 1) ? Wk : Wv);
    float* dst = (mat == 0) ? g_rpre : ((mat == 1) ? g_k : g_v);
    gemv_rows_async(W, g_x, rowbase, dst, nullptr);
}

// K3: h = x + Wo @ y. grid.x = D/ROWS = 1024
__global__ void __launch_bounds__(GTHREADS) gemv_o_kernel(const float* __restrict__ Wo) {
    int rowbase = blockIdx.x * ROWS;
    gemv_rows_async(Wo, g_y, rowbase, g_h, g_x);
}

// ---------------------------------------------------------------------------
// K2: elementwise (decay, RoPE, Kalman gate) -> y
// ---------------------------------------------------------------------------
__global__ void elemwise_kernel(const float* __restrict__ step_pos,
                                const float* __restrict__ state_num,
                                const float* __restrict__ state_den,
                                const float* __restrict__ state_var,
                                const float* __restrict__ raw_decay,
                                const float* __restrict__ pn_param,
                                const float* __restrict__ on_param,
                                const float* __restrict__ W_time) {
    int i = blockIdx.x * 256 + threadIdx.x;
    if (i >= D) return;

    float k = g_k[i];
    float v = g_v[i];
    if (i < 2 * M_TIME) {
        int m = i >> 1;
        float th = step_pos[0] * W_time[m];
        float c, s;
        sincosf(th, &s, &c);
        float v0 = g_v[2 * m];
        float v1 = g_v[2 * m + 1];
        v = (i & 1) ? (v0 * s + v1 * c) : (v0 * c - v1 * s);
    }

    float sp = softplusf(raw_decay[i]);
    float rate = fmaxf(-sp, -30.f);
    float lam = fmaxf(expf(rate), 1e-6f);
    float pn = fminf(fmaxf(softplusf(pn_param[0]), 1e-6f), 1e4f);
    float on = fminf(fmaxf(softplusf(on_param[0]), 1e-6f), 1e4f);

    float sn = state_num[i] * lam;
    float sd = state_den[i] * lam;
    float sv = state_var[i] * lam * lam + pn;

    float r = 1.f / (1.f + expf(-g_rpre[i]));
    float w = expf(fminf(k, 30.f));
    float pred_state = sn / (sd + 1e-6f);
    float msg = w * v;
    float resid = msg - pred_state;
    float obs_var = expf(fminf(-k, 30.f)) * on + 1e-6f;
    float gain = sv / (sv + obs_var);
    gain = fminf(fmaxf(gain, 1e-6f), 1.f - 1e-6f);
    float new_state = pred_state + gain * resid;
    g_y[i] = r * new_state;
}

// ---------------------------------------------------------------------------
// K4: exact KWTA_K-th-largest (radix select) + threshold. 1 block, 1024 thr.
// ---------------------------------------------------------------------------
__global__ void topk_kernel(float* __restrict__ out) {
    __shared__ unsigned hist[256];
    __shared__ unsigned s_prefix;
    __shared__ int s_K;
    __shared__ float s_thresh;

    if (threadIdx.x == 0) { s_prefix = 0u; s_K = KWTA_K; }
    __syncthreads();

    for (int pass = 3; pass >= 0; pass--) {
        if (threadIdx.x < 256) hist[threadIdx.x] = 0u;
        __syncthreads();
        unsigned prefmask = (pass == 3) ? 0u : (0xFFFFFFFFu << ((pass + 1) * 8));
        unsigned pref = s_prefix;
        for (int i = threadIdx.x; i < D; i += 1024) {
            unsigned u = __float_as_uint(g_h[i]);
            unsigned key = (u & 0x80000000u) ? ~u : (u | 0x80000000u);
            if ((key & prefmask) == (pref & prefmask)) {
                atomicAdd(&hist[(key >> (pass * 8)) & 255u], 1u);
            }
        }
        __syncthreads();
        if (threadIdx.x == 0) {
            int K = s_K;
            unsigned cum = 0;
            int b = 255;
            for (; b >= 0; b--) {
                cum += hist[b];
                if ((int)cum >= K) break;
            }
            s_K = K - (int)(cum - hist[b]);
            s_prefix = s_prefix | ((unsigned)b << (pass * 8));
        }
        __syncthreads();
    }

    if (threadIdx.x == 0) {
        unsigned key = s_prefix;
        unsigned u = (key & 0x80000000u) ? (key ^ 0x80000000u) : ~key;
        s_thresh = __uint_as_float(u);
    }
    __syncthreads();

    float th = s_thresh;
    for (int i = threadIdx.x; i < D; i += 1024) {
        float h = g_h[i];
        out[i] = (h >= th) ? h : 0.f;
    }
}

// ---------------------------------------------------------------------------
// Launch
// ---------------------------------------------------------------------------
extern "C" void kernel_launch(void* const* d_in, const int* in_sizes, int n_in,
                              void* d_out, int out_size) {
    const float* x_in      = (const float*)d_in[0];
    const float* step_pos  = (const float*)d_in[1];
    const float* pred      = (const float*)d_in[2];
    const float* state_num = (const float*)d_in[3];
    const float* state_den = (const float*)d_in[4];
    const float* state_var = (const float*)d_in[5];
    const float* Wr        = (const float*)d_in[6];
    const float* Wk        = (const float*)d_in[7];
    const float* Wv        = (const float*)d_in[8];
    const float* Wo        = (const float*)d_in[9];
    const float* raw_decay = (const float*)d_in[10];
    const float* pn_param  = (const float*)d_in[11];
    const float* on_param  = (const float*)d_in[12];
    const float* g_norm    = (const float*)d_in[13];
    const float* W_time    = (const float*)d_in[14];
    float* out = (float*)d_out;

    // Allow 64KB dynamic smem on the GEMV kernels (idempotent, host-side only)
    cudaFuncSetAttribute(gemv3_kernel,
                         cudaFuncAttributeMaxDynamicSharedMemorySize, SMEM_BYTES);
    cudaFuncSetAttribute(gemv_o_kernel,
                         cudaFuncAttributeMaxDynamicSharedMemorySize, SMEM_BYTES);

    rmsnorm_kernel<<<1, 1024>>>(x_in, pred, g_norm);
    gemv3_kernel<<<3 * (D / ROWS), GTHREADS, SMEM_BYTES>>>(Wr, Wk, Wv);
    elemwise_kernel<<<D / 256, 256>>>(step_pos, state_num, state_den, state_var,
                                      raw_decay, pn_param, on_param, W_time);
    gemv_o_kernel<<<D / ROWS, GTHREADS, SMEM_BYTES>>>(Wo);
    topk_kernel<<<1, 1024>>>(out);
}